// round 15
// baseline (speedup 1.0000x reference)
#include <cuda_runtime.h>
#include <cuda_bf16.h>
#include <mma.h>
#include <stdint.h>
#include <math.h>

using namespace nvcuda;

#define BB 4
#define SS 512
#define VV 50257
#define DD 768
#define HH 12
#define DHH 64
#define NLAYER 2
#define DFFN 3072
#define LAT_START 64
#define NLAT 6
#define ATT_SCALE 0.125f

#define WQKV_T_OFF 0
#define WO_T_OFF   (2304*768)
#define W1_T_OFF   (2304*768 + 768*768)
#define W2_T_OFF   (2304*768 + 768*768 + 3072*768)
#define PER_L      (2304*768 + 768*768 + 3072*768 + 768*3072)

#define LDSK 24
#define A_ELE (128*LDSK)          // 3072
#define B_ELE (256*LDSK)          // 6144
#define BUF_ELE (2*A_ELE + 2*B_ELE) // 18432 elems = 36864 B
#define TG_SMEM (2*BUF_ELE*2)     // 73728 B

static __device__ float g_embeds[BB*SS*DD];
static __device__ float g_X   [BB*SS*DD];
static __device__ float g_H   [BB*SS*DD];
static __device__ float g_HID [BB*SS*DD];
static __device__ float g_QKV [BB*SS*3*DD];
static __device__ float g_CTX [BB*SS*DD];
static __device__ float g_G   [BB*SS*DFFN];
static __device__ float g_K   [NLAYER*BB*HH*SS*DHH];
static __device__ float g_V   [NLAYER*BB*HH*SS*DHH];
static __device__ float g_part[24*4*DFFN];
static __device__ float g_nll [BB*(SS-1)];
static __device__ __align__(16) __nv_bfloat16 g_Whi[2*PER_L];
static __device__ __align__(16) __nv_bfloat16 g_Wlo[2*PER_L];
static __device__ __align__(16) __nv_bfloat16 g_Vhi[(size_t)VV*DD];
static __device__ __align__(16) __nv_bfloat16 g_Vlo[(size_t)VV*DD];
static __device__ __align__(16) __nv_bfloat16 g_Ahi[BB*SS*DFFN];
static __device__ __align__(16) __nv_bfloat16 g_Alo[BB*SS*DFFN];

__device__ __forceinline__ float wrsum(float v) {
    #pragma unroll
    for (int o = 16; o; o >>= 1) v += __shfl_xor_sync(0xffffffffu, v, o);
    return v;
}
__device__ __forceinline__ float wrmax(float v) {
    #pragma unroll
    for (int o = 16; o; o >>= 1) v = fmaxf(v, __shfl_xor_sync(0xffffffffu, v, o));
    return v;
}
__device__ __forceinline__ float gelu_tanh(float u) {
    return 0.5f*u*(1.f + tanhf(0.7978845608028654f*(u + 0.044715f*u*u*u)));
}
// polynomial exp for d <= 0 (FMA pipe, no MUFU); rel err ~2e-6
__device__ __forceinline__ float fexp(float d) {
    float t = d * 1.4426950408889634f;
    t = fmaxf(t, -127.0f);
    float fi = rintf(t);
    float f = t - fi;
    int i = (int)fi;
    float p = 0.0013333558f;
    p = fmaf(p, f, 0.0096181291f);
    p = fmaf(p, f, 0.0555041087f);
    p = fmaf(p, f, 0.2402265069f);
    p = fmaf(p, f, 0.6931471806f);
    p = fmaf(p, f, 1.0f);
    float sc = __int_as_float((i + 127) << 23);
    return p * sc;
}

__global__ void cvt_split(const float* __restrict__ s, __nv_bfloat16* __restrict__ hi,
                          __nv_bfloat16* __restrict__ lo, int n) {
    int i = blockIdx.x * 256 + threadIdx.x;
    if (i >= n) return;
    float v = s[i];
    __nv_bfloat16 h = __float2bfloat16(v);
    hi[i] = h;
    lo[i] = __float2bfloat16(v - __bfloat162float(h));
}

__global__ void cvt_tr(const float* __restrict__ W, __nv_bfloat16* __restrict__ hiT,
                       __nv_bfloat16* __restrict__ loT, int K, int N) {
    __shared__ float t[32][33];
    int k0 = blockIdx.y * 32, n0 = blockIdx.x * 32;
    for (int i = threadIdx.y; i < 32; i += 8)
        t[i][threadIdx.x] = W[(size_t)(k0 + i)*N + n0 + threadIdx.x];
    __syncthreads();
    for (int i = threadIdx.y; i < 32; i += 8) {
        int n = n0 + i, k = k0 + threadIdx.x;
        float v = t[threadIdx.x][i];
        __nv_bfloat16 h = __float2bfloat16(v);
        hiT[(size_t)n*K + k] = h;
        loT[(size_t)n*K + k] = __float2bfloat16(v - __bfloat162float(h));
    }
}

// HMMA split-bf16 GEMM v2. C[M,N]=epi(A x B^T), B[N,K] row-major.
// Block tile 128x256, 8 warps of 64x64 (2x4), K chunks of 16, double-buffered.
template<int ACT, int HASRES, int HASBIAS>
__global__ void __launch_bounds__(256)
tgemm(const __nv_bfloat16* __restrict__ Ah, const __nv_bfloat16* __restrict__ Al,
      const __nv_bfloat16* __restrict__ Bh, const __nv_bfloat16* __restrict__ Bl,
      const float* __restrict__ bias, const float* __restrict__ res,
      float* __restrict__ C, int M, int N, int K, int ldc) {
    extern __shared__ __align__(16) __nv_bfloat16 smem[];
    int tid = threadIdx.x, wid = tid >> 5, lane = tid & 31;
    int row0 = blockIdx.x * 128, col0 = blockIdx.y * 256;
    int wm = wid >> 2, wn = wid & 3;   // warp tile rows wm*64, cols wn*64

    wmma::fragment<wmma::accumulator, 16, 16, 16, float> acc[4][4];
    #pragma unroll
    for (int m = 0; m < 4; m++)
        #pragma unroll
        for (int n = 0; n < 4; n++) wmma::fill_fragment(acc[m][n], 0.0f);

    int KC = K >> 4;

    // load chunk 0 into buffer 0
    #pragma unroll
    for (int j = 0; j < 6; j++) {
        int i = tid + j*256;
        uint4 v = make_uint4(0,0,0,0);
        __nv_bfloat16* dst;
        if (i < 512) {
            int var = i >> 8, e = i & 255, r = e >> 1, g = (e & 1)*8;
            int gr = row0 + r;
            const __nv_bfloat16* s = var ? Al : Ah;
            if (gr < M) v = *(const uint4*)(s + (size_t)gr*K + g);
            dst = smem + var*A_ELE + r*LDSK + g;
        } else {
            int i2 = i - 512;
            int var = i2 >> 9, e = i2 & 511, r = e >> 1, g = (e & 1)*8;
            int gn = col0 + r;
            const __nv_bfloat16* s = var ? Bl : Bh;
            if (gn < N) v = *(const uint4*)(s + (size_t)gn*K + g);
            dst = smem + 2*A_ELE + var*B_ELE + r*LDSK + g;
        }
        *(uint4*)dst = v;
    }
    __syncthreads();

    for (int kc = 0; kc < KC; kc++) {
        int b = kc & 1;
        uint4 pr[6];
        if (kc + 1 < KC) {
            #pragma unroll
            for (int j = 0; j < 6; j++) {
                int i = tid + j*256;
                pr[j] = make_uint4(0,0,0,0);
                if (i < 512) {
                    int var = i >> 8, e = i & 255, r = e >> 1, g = (e & 1)*8;
                    int gr = row0 + r;
                    const __nv_bfloat16* s = var ? Al : Ah;
                    if (gr < M) pr[j] = *(const uint4*)(s + (size_t)gr*K + (kc+1)*16 + g);
                } else {
                    int i2 = i - 512;
                    int var = i2 >> 9, e = i2 & 511, r = e >> 1, g = (e & 1)*8;
                    int gn = col0 + r;
                    const __nv_bfloat16* s = var ? Bl : Bh;
                    if (gn < N) pr[j] = *(const uint4*)(s + (size_t)gn*K + (kc+1)*16 + g);
                }
            }
        }

        const __nv_bfloat16* bufp = smem + b*BUF_ELE;
        wmma::fragment<wmma::matrix_b, 16, 16, 16, __nv_bfloat16, wmma::col_major> fbh[4], fbl[4];
        #pragma unroll
        for (int n = 0; n < 4; n++) {
            wmma::load_matrix_sync(fbh[n], bufp + 2*A_ELE + (wn*64 + n*16)*LDSK, LDSK);
            wmma::load_matrix_sync(fbl[n], bufp + 2*A_ELE + B_ELE + (wn*64 + n*16)*LDSK, LDSK);
        }
        #pragma unroll
        for (int m = 0; m < 4; m++) {
            wmma::fragment<wmma::matrix_a, 16, 16, 16, __nv_bfloat16, wmma::row_major> fah, fal;
            wmma::load_matrix_sync(fah, bufp + (wm*64 + m*16)*LDSK, LDSK);
            wmma::load_matrix_sync(fal, bufp + A_ELE + (wm*64 + m*16)*LDSK, LDSK);
            #pragma unroll
            for (int n = 0; n < 4; n++) {
                wmma::mma_sync(acc[m][n], fah, fbh[n], acc[m][n]);
                wmma::mma_sync(acc[m][n], fah, fbl[n], acc[m][n]);
                wmma::mma_sync(acc[m][n], fal, fbh[n], acc[m][n]);
            }
        }

        if (kc + 1 < KC) {
            __nv_bfloat16* nbuf = smem + ((kc+1)&1)*BUF_ELE;
            #pragma unroll
            for (int j = 0; j < 6; j++) {
                int i = tid + j*256;
                __nv_bfloat16* dst;
                if (i < 512) {
                    int var = i >> 8, e = i & 255, r = e >> 1, g = (e & 1)*8;
                    dst = nbuf + var*A_ELE + r*LDSK + g;
                } else {
                    int i2 = i - 512;
                    int var = i2 >> 9, e = i2 & 511, r = e >> 1, g = (e & 1)*8;
                    dst = nbuf + 2*A_ELE + var*B_ELE + r*LDSK + g;
                }
                *(uint4*)dst = pr[j];
            }
        }
        __syncthreads();
    }

    // epilogue: two 32-row stages per warp through smem (stride 68 floats)
    float* fsm = (float*)smem;
    float* wsm = fsm + wid * (32*68);
    int gc0 = col0 + wn*64 + lane;
    int gc1 = gc0 + 32;
    float bv0 = (HASBIAS && gc0 < N) ? bias[gc0] : 0.f;
    float bv1 = (HASBIAS && gc1 < N) ? bias[gc1] : 0.f;
    #pragma unroll
    for (int s = 0; s < 2; s++) {
        #pragma unroll
        for (int mm = 0; mm < 2; mm++)
            #pragma unroll
            for (int n = 0; n < 4; n++)
                wmma::store_matrix_sync(wsm + mm*16*68 + n*16, acc[s*2+mm][n], 68, wmma::mem_row_major);
        __syncwarp();
        for (int rr = 0; rr < 32; rr++) {
            int gr = row0 + wm*64 + s*32 + rr;
            if (gr >= M) break;
            float v0 = wsm[rr*68 + lane]      + bv0;
            float v1 = wsm[rr*68 + lane + 32] + bv1;
            if (ACT) { v0 = gelu_tanh(v0); v1 = gelu_tanh(v1); }
            if (HASRES) {
                if (gc0 < N) v0 += res[(size_t)gr*ldc + gc0];
                if (gc1 < N) v1 += res[(size_t)gr*ldc + gc1];
            }
            if (gc0 < N) C[(size_t)gr*ldc + gc0] = v0;
            if (gc1 < N) C[(size_t)gr*ldc + gc1] = v1;
        }
        __syncwarp();
    }
}

__global__ void embed_init_kernel(const int* __restrict__ ids, const float* __restrict__ wte) {
    int idx = blockIdx.x * 256 + threadIdx.x;
    if (idx >= BB*SS*DD) return;
    int r = idx / DD, d = idx - r*DD;
    g_embeds[idx] = wte[(size_t)ids[r]*DD + d];
}
__global__ void build_x_kernel(const int* __restrict__ pos_ids, const float* __restrict__ wpe,
                               int qs, int qc) {
    int idx = blockIdx.x * 256 + threadIdx.x;
    if (idx >= BB*qc*DD) return;
    int r = idx / DD, d = idx - r*DD;
    int b = r / qc, t = r - b*qc;
    int s = qs + t;
    g_X[idx] = g_embeds[((size_t)b*SS + s)*DD + d] + wpe[(size_t)pos_ids[b*SS + s]*DD + d];
}
__global__ void ln_kernel(const float* __restrict__ in, float* __restrict__ out,
                          const float* __restrict__ gam, const float* __restrict__ bet,
                          int qc, int qs, int scatter) {
    int r = blockIdx.x;
    const float* x = in + (size_t)r*DD;
    int tid = threadIdx.x;
    float x0 = x[tid], x1 = x[tid+256], x2 = x[tid+512];
    __shared__ float sh[8];
    float s = wrsum(x0 + x1 + x2);
    if ((tid & 31) == 0) sh[tid >> 5] = s;
    __syncthreads();
    if (tid == 0) { float t = 0.f; for (int i = 0; i < 8; i++) t += sh[i]; sh[0] = t * (1.f/DD); }
    __syncthreads();
    float mean = sh[0];
    float d0 = x0 - mean, d1 = x1 - mean, d2 = x2 - mean;
    __syncthreads();
    float q = wrsum(d0*d0 + d1*d1 + d2*d2);
    if ((tid & 31) == 0) sh[tid >> 5] = q;
    __syncthreads();
    if (tid == 0) { float t = 0.f; for (int i = 0; i < 8; i++) t += sh[i]; sh[0] = rsqrtf(t*(1.f/DD) + 1e-5f); }
    __syncthreads();
    float rstd = sh[0];
    int orow = r;
    if (scatter) { int b = r / qc, t = r - b*qc; orow = b*SS + qs + t; }
    float* o = out + (size_t)orow*DD;
    o[tid]     = d0*rstd*gam[tid]     + bet[tid];
    o[tid+256] = d1*rstd*gam[tid+256] + bet[tid+256];
    o[tid+512] = d2*rstd*gam[tid+512] + bet[tid+512];
}

__global__ void gemv4_part(const float* __restrict__ A, const float* __restrict__ W, int N, int K) {
    __shared__ float Ash[4][128];
    int tid = threadIdx.x;
    int k0 = blockIdx.y * 128;
    for (int i = tid; i < 512; i += 128) {
        int r = i >> 7, k = i & 127;
        Ash[r][k] = A[(size_t)r*K + k0 + k];
    }
    __syncthreads();
    int n = blockIdx.x * 128 + tid;
    const float* wp = W + (size_t)k0*N + n;
    float s0=0.f, s1=0.f, s2=0.f, s3=0.f;
    #pragma unroll 8
    for (int k = 0; k < 128; k++) {
        float w = wp[(size_t)k*N];
        s0 = fmaf(w, Ash[0][k], s0);
        s1 = fmaf(w, Ash[1][k], s1);
        s2 = fmaf(w, Ash[2][k], s2);
        s3 = fmaf(w, Ash[3][k], s3);
    }
    float* pp = g_part + (size_t)blockIdx.y*4*DFFN + n;
    pp[0] = s0; pp[DFFN] = s1; pp[2*DFFN] = s2; pp[3*DFFN] = s3;
}
template<int ACT, int HASRES>
__global__ void gemv4_red(const float* __restrict__ bias, const float* __restrict__ res,
                          float* __restrict__ C, int N, int kch) {
    int n = blockIdx.x * 256 + threadIdx.x;
    if (n >= N) return;
    #pragma unroll
    for (int r = 0; r < 4; r++) {
        float s = bias[n];
        for (int c = 0; c < kch; c++) s += g_part[(size_t)c*4*DFFN + r*DFFN + n];
        if (ACT)    s = gelu_tanh(s);
        if (HASRES) s += res[(size_t)r*N + n];
        C[(size_t)r*N + n] = s;
    }
}

__global__ void kv_scatter(int l, int qs, int qc) {
    int idx = blockIdx.x * 256 + threadIdx.x;
    if (idx >= BB*qc*DD) return;
    int r = idx / DD, d = idx - r*DD;
    int b = r / qc, t = r - b*qc;
    int h = d >> 6, dh = d & 63;
    size_t c = ((size_t)((l*BB + b)*HH + h)*SS + qs + t)*DHH + dh;
    g_K[c] = g_QKV[(size_t)r*(3*DD) + DD   + d];
    g_V[c] = g_QKV[(size_t)r*(3*DD) + 2*DD + d];
}

__global__ void attn_kernel(int l, int qs, int qc, const int* __restrict__ amask) {
    __shared__ float qsh[8][4][64];
    int w = threadIdx.x >> 5, lane = threadIdx.x & 31;
    int nqt = (qc + 3) >> 2;
    int gw = blockIdx.x * 8 + w;
    if (gw >= nqt * BB * HH) return;
    int h = gw % HH, r1 = gw / HH, b = r1 % BB, qt = r1 / BB;
    int t0 = qt * 4;
    #pragma unroll
    for (int i = 0; i < 4; i++) {
        int t = t0 + i; if (t >= qc) t = qc - 1;
        const float* qp = g_QKV + (size_t)(b*qc + t)*(3*DD) + h*DHH;
        qsh[w][i][lane]      = qp[lane]      * ATT_SCALE;
        qsh[w][i][lane + 32] = qp[lane + 32] * ATT_SCALE;
    }
    __syncwarp();
    int qlast = min(t0 + 3, qc - 1);
    int qmax = qs + qlast;
    const float* kc = g_K + (size_t)((l*BB + b)*HH + h)*SS*DHH;
    const float* vc = g_V + (size_t)((l*BB + b)*HH + h)*SS*DHH;
    float m0=-1e30f,m1=-1e30f,m2=-1e30f,m3=-1e30f, dn0=0.f,dn1=0.f,dn2=0.f,dn3=0.f;
    float2 a0={0.f,0.f},a1={0.f,0.f},a2={0.f,0.f},a3={0.f,0.f};
    for (int j0 = 0; j0 <= qmax; j0 += 32) {
        int j = j0 + lane;
        float s0=-1e30f,s1=-1e30f,s2=-1e30f,s3=-1e30f;
        if (j <= qmax && amask[b*SS + j] != 0) {
            const float4* kr = (const float4*)(kc + (size_t)j*DHH);
            float u0=0.f,u1=0.f,u2=0.f,u3=0.f;
            #pragma unroll
            for (int i2 = 0; i2 < 16; i2++) {
                float4 kv = kr[i2];
                float4 q0 = *(const float4*)&qsh[w][0][i2*4];
                float4 q1 = *(const float4*)&qsh[w][1][i2*4];
                float4 q2 = *(const float4*)&qsh[w][2][i2*4];
                float4 q3 = *(const float4*)&qsh[w][3][i2*4];
                u0 += kv.x*q0.x + kv.y*q0.y + kv.z*q0.z + kv.w*q0.w;
                u1 += kv.x*q1.x + kv.y*q1.y + kv.z*q1.z + kv.w*q1.w;
                u2 += kv.x*q2.x + kv.y*q2.y + kv.z*q2.z + kv.w*q2.w;
                u3 += kv.x*q3.x + kv.y*q3.y + kv.z*q3.z + kv.w*q3.w;
            }
            s0 = (j <= qs + t0    ) ? u0 : -1e30f;
            s1 = (j <= qs + t0 + 1) ? u1 : -1e30f;
            s2 = (j <= qs + t0 + 2) ? u2 : -1e30f;
            s3 = (j <= qs + t0 + 3) ? u3 : -1e30f;
        }
        float n0 = fmaxf(m0, wrmax(s0)), n1 = fmaxf(m1, wrmax(s1));
        float n2 = fmaxf(m2, wrmax(s2)), n3 = fmaxf(m3, wrmax(s3));
        float p0 = __expf(s0-n0), p1 = __expf(s1-n1), p2 = __expf(s2-n2), p3 = __expf(s3-n3);
        float q0 = wrsum(p0), q1 = wrsum(p1), q2 = wrsum(p2), q3 = wrsum(p3);
        float e0 = __expf(m0-n0), e1 = __expf(m1-n1), e2 = __expf(m2-n2), e3 = __expf(m3-n3);
        dn0 = dn0*e0 + q0; a0.x *= e0; a0.y *= e0; m0 = n0;
        dn1 = dn1*e1 + q1; a1.x *= e1; a1.y *= e1; m1 = n1;
        dn2 = dn2*e2 + q2; a2.x *= e2; a2.y *= e2; m2 = n2;
        dn3 = dn3*e3 + q3; a3.x *= e3; a3.y *= e3; m3 = n3;
        int jc = min(32, qmax - j0 + 1);
        for (int jj = 0; jj < jc; jj++) {
            float2 vv = *(const float2*)(vc + (size_t)(j0 + jj)*DHH + lane*2);
            float w0 = __shfl_sync(0xffffffffu, p0, jj), w1 = __shfl_sync(0xffffffffu, p1, jj);
            float w2 = __shfl_sync(0xffffffffu, p2, jj), w3 = __shfl_sync(0xffffffffu, p3, jj);
            a0.x = fmaf(w0, vv.x, a0.x); a0.y = fmaf(w0, vv.y, a0.y);
            a1.x = fmaf(w1, vv.x, a1.x); a1.y = fmaf(w1, vv.y, a1.y);
            a2.x = fmaf(w2, vv.x, a2.x); a2.y = fmaf(w2, vv.y, a2.y);
            a3.x = fmaf(w3, vv.x, a3.x); a3.y = fmaf(w3, vv.y, a3.y);
        }
    }
    float2 ac[4] = {a0,a1,a2,a3};
    float dn[4] = {dn0,dn1,dn2,dn3};
    #pragma unroll
    for (int i = 0; i < 4; i++) {
        int t = t0 + i;
        if (t < qc) {
            float inv = 1.f / dn[i];
            *(float2*)&g_CTX[(size_t)(b*qc + t)*DD + h*DHH + lane*2] =
                make_float2(ac[i].x*inv, ac[i].y*inv);
        }
    }
}

__global__ void latent_update_kernel(int slot) {
    int idx = blockIdx.x * 256 + threadIdx.x;
    if (idx >= BB*DD) return;
    int b = idx / DD, d = idx - b*DD;
    g_embeds[((size_t)b*SS + slot)*DD + d] = g_HID[((size_t)b*SS + slot - 1)*DD + d];
}

// single-pass online-softmax NLL (poly exp on FMA pipe)
__global__ void loss_row_kernel(const float* __restrict__ logits, const int* __restrict__ labels) {
    int r = blockIdx.x;
    int b = r / (SS-1), t = r - b*(SS-1);
    const float* x = logits + ((size_t)(b*SS + t))*VV;
    int tid = threadIdx.x;
    float mx = -1e30f, s = 0.f;
    for (int i = tid; i < VV; i += 256) {
        float v = x[i];
        float nm = fmaxf(mx, v);
        s = s * fexp(mx - nm) + fexp(v - nm);
        mx = nm;
    }
    // warp combine
    #pragma unroll
    for (int o = 16; o; o >>= 1) {
        float om = __shfl_xor_sync(0xffffffffu, mx, o);
        float os = __shfl_xor_sync(0xffffffffu, s, o);
        float nm = fmaxf(mx, om);
        s = s * fexp(mx - nm) + os * fexp(om - nm);
        mx = nm;
    }
    __shared__ float shm[8], shs[8];
    if ((tid & 31) == 0) { shm[tid >> 5] = mx; shs[tid >> 5] = s; }
    __syncthreads();
    if (tid == 0) {
        float M2 = shm[0], S2 = shs[0];
        for (int i = 1; i < 8; i++) {
            float nm = fmaxf(M2, shm[i]);
            S2 = S2 * fexp(M2 - nm) + shs[i] * fexp(shm[i] - nm);
            M2 = nm;
        }
        g_nll[r] = logf(S2) + M2 - x[labels[b*SS + t + 1]];
    }
}
__global__ void loss_final_kernel(float* out) {
    int tid = threadIdx.x;
    __shared__ float sh[8];
    float s = 0.f;
    for (int i = tid; i < BB*(SS-1); i += 256) s += g_nll[i];
    s = wrsum(s);
    if ((tid & 31) == 0) sh[tid >> 5] = s;
    __syncthreads();
    if (tid == 0) {
        float t = 0.f; for (int i = 0; i < 8; i++) t += sh[i];
        out[0] = t / (float)(BB*(SS-1));
    }
}

extern "C" void kernel_launch(void* const* d_in, const int* in_sizes, int n_in,
                              void* d_out, int out_size) {
    const int*   input_ids = (const int*)d_in[0];
    const int*   amask     = (const int*)d_in[1];
    const int*   labels    = (const int*)d_in[2];
    const int*   pos_ids   = (const int*)d_in[3];
    const float* wte   = (const float*)d_in[4];
    const float* wpe   = (const float*)d_in[5];
    const float* ln1_g = (const float*)d_in[6];
    const float* ln1_b = (const float*)d_in[7];
    const float* Wqkv  = (const float*)d_in[8];
    const float* bqkv  = (const float*)d_in[9];
    const float* Wo    = (const float*)d_in[10];
    const float* bo    = (const float*)d_in[11];
    const float* ln2_g = (const float*)d_in[12];
    const float* ln2_b = (const float*)d_in[13];
    const float* W1    = (const float*)d_in[14];
    const float* b1    = (const float*)d_in[15];
    const float* W2    = (const float*)d_in[16];
    const float* b2    = (const float*)d_in[17];
    const float* lnf_g = (const float*)d_in[18];
    const float* lnf_b = (const float*)d_in[19];

    float* out    = (float*)d_out;
    float* logits = out + 1;

    cudaFuncSetAttribute(tgemm<0,0,0>, cudaFuncAttributeMaxDynamicSharedMemorySize, TG_SMEM);
    cudaFuncSetAttribute(tgemm<0,0,1>, cudaFuncAttributeMaxDynamicSharedMemorySize, TG_SMEM);
    cudaFuncSetAttribute(tgemm<0,1,1>, cudaFuncAttributeMaxDynamicSharedMemorySize, TG_SMEM);
    cudaFuncSetAttribute(tgemm<1,0,1>, cudaFuncAttributeMaxDynamicSharedMemorySize, TG_SMEM);

    float *pX, *pH, *pHID, *pQKV, *pCTX, *pG;
    cudaGetSymbolAddress((void**)&pX,   g_X);
    cudaGetSymbolAddress((void**)&pH,   g_H);
    cudaGetSymbolAddress((void**)&pHID, g_HID);
    cudaGetSymbolAddress((void**)&pQKV, g_QKV);
    cudaGetSymbolAddress((void**)&pCTX, g_CTX);
    cudaGetSymbolAddress((void**)&pG,   g_G);
    __nv_bfloat16 *pAh, *pAl, *pWh, *pWl, *pVh, *pVl;
    cudaGetSymbolAddress((void**)&pAh, g_Ahi);
    cudaGetSymbolAddress((void**)&pAl, g_Alo);
    cudaGetSymbolAddress((void**)&pWh, g_Whi);
    cudaGetSymbolAddress((void**)&pWl, g_Wlo);
    cudaGetSymbolAddress((void**)&pVh, g_Vhi);
    cudaGetSymbolAddress((void**)&pVl, g_Vlo);

    embed_init_kernel<<<(BB*SS*DD + 255)/256, 256>>>(input_ids, wte);
    cvt_split<<<(VV*DD + 255)/256, 256>>>(wte, pVh, pVl, VV*DD);
    for (int l = 0; l < NLAYER; l++) {
        __nv_bfloat16* wh = pWh + (size_t)l*PER_L;
        __nv_bfloat16* wl = pWl + (size_t)l*PER_L;
        cvt_tr<<<dim3(2304/32, 768/32),  dim3(32,8)>>>(Wqkv + (size_t)l*DD*3*DD, wh + WQKV_T_OFF, wl + WQKV_T_OFF, 768, 2304);
        cvt_tr<<<dim3(768/32,  768/32),  dim3(32,8)>>>(Wo   + (size_t)l*DD*DD,   wh + WO_T_OFF,   wl + WO_T_OFF,   768, 768);
        cvt_tr<<<dim3(3072/32, 768/32),  dim3(32,8)>>>(W1   + (size_t)l*DD*DFFN, wh + W1_T_OFF,   wl + W1_T_OFF,   768, 3072);
        cvt_tr<<<dim3(768/32,  3072/32), dim3(32,8)>>>(W2   + (size_t)l*DFFN*DD, wh + W2_T_OFF,   wl + W2_T_OFF,   3072, 768);
    }

    const int QS[7] = {0, 64, 65, 66, 67, 68, 69};
    const int QC[7] = {64, 1,  1,  1,  1,  1,  SS - 69};

    for (int p = 0; p < 7; p++) {
        int qs = QS[p], qc = QC[p];
        int M = BB * qc;
        int mt = (M + 127)/128;

        build_x_kernel<<<(M*DD + 255)/256, 256>>>(pos_ids, wpe, qs, qc);

        for (int l = 0; l < NLAYER; l++) {
            __nv_bfloat16* wh = pWh + (size_t)l*PER_L;
            __nv_bfloat16* wl = pWl + (size_t)l*PER_L;
            const float* Wq  = Wqkv + (size_t)l*DD*3*DD;  const float* bq  = bqkv + (size_t)l*3*DD;
            const float* Wol = Wo   + (size_t)l*DD*DD;    const float* bol = bo   + (size_t)l*DD;
            const float* W1l = W1   + (size_t)l*DD*DFFN;  const float* b1l = b1   + (size_t)l*DFFN;
            const float* W2l = W2   + (size_t)l*DFFN*DD;  const float* b2l = b2   + (size_t)l*DD;

            ln_kernel<<<M, 256>>>(pX, pH, ln1_g + l*DD, ln1_b + l*DD, qc, qs, 0);

            if (qc == 1) {
                gemv4_part<<<dim3(3*DD/128, DD/128), 128>>>(pH, Wq, 3*DD, DD);
                gemv4_red<0,0><<<(3*DD + 255)/256, 256>>>(bq, 0, pQKV, 3*DD, DD/128);
            } else {
                cvt_split<<<(M*DD + 255)/256, 256>>>(pH, pAh, pAl, M*DD);
                tgemm<0,0,1><<<dim3(mt, 9), 256, TG_SMEM>>>(pAh, pAl, wh + WQKV_T_OFF, wl + WQKV_T_OFF,
                                                            bq, 0, pQKV, M, 3*DD, DD, 3*DD);
            }

            kv_scatter<<<(M*DD + 255)/256, 256>>>(l, qs, qc);
            attn_kernel<<<(((qc+3)/4)*BB*HH + 7)/8, 256>>>(l, qs, qc, amask);

            if (qc == 1) {
                gemv4_part<<<dim3(DD/128, DD/128), 128>>>(pCTX, Wol, DD, DD);
                gemv4_red<0,1><<<(DD + 255)/256, 256>>>(bol, pX, pX, DD, DD/128);
            } else {
                cvt_split<<<(M*DD + 255)/256, 256>>>(pCTX, pAh, pAl, M*DD);
                tgemm<0,1,1><<<dim3(mt, 3), 256, TG_SMEM>>>(pAh, pAl, wh + WO_T_OFF, wl + WO_T_OFF,
                                                            bol, pX, pX, M, DD, DD, DD);
            }

            ln_kernel<<<M, 256>>>(pX, pH, ln2_g + l*DD, ln2_b + l*DD, qc, qs, 0);

            if (qc == 1) {
                gemv4_part<<<dim3(DFFN/128, DD/128), 128>>>(pH, W1l, DFFN, DD);
                gemv4_red<1,0><<<(DFFN + 255)/256, 256>>>(b1l, 0, pG, DFFN, DD/128);
                gemv4_part<<<dim3(DD/128, DFFN/128), 128>>>(pG, W2l, DD, DFFN);
                gemv4_red<0,1><<<(DD + 255)/256, 256>>>(b2l, pX, pX, DD, DFFN/128);
            } else {
                cvt_split<<<(M*DD + 255)/256, 256>>>(pH, pAh, pAl, M*DD);
                tgemm<1,0,1><<<dim3(mt, 12), 256, TG_SMEM>>>(pAh, pAl, wh + W1_T_OFF, wl + W1_T_OFF,
                                                             b1l, 0, pG, M, DFFN, DD, DFFN);
                cvt_split<<<(M*DFFN + 255)/256, 256>>>(pG, pAh, pAl, M*DFFN);
                tgemm<0,1,1><<<dim3(mt, 3), 256, TG_SMEM>>>(pAh, pAl, wh + W2_T_OFF, wl + W2_T_OFF,
                                                            b2l, pX, pX, M, DD, DFFN, DD);
            }
        }

        ln_kernel<<<M, 256>>>(pX, pHID, lnf_g, lnf_b, qc, qs, 1);

        if (p < NLAT) latent_update_kernel<<<(BB*DD + 255)/256, 256>>>(LAT_START + p);
    }

    cvt_split<<<(BB*SS*DD + 255)/256, 256>>>(pHID, pAh, pAl, BB*SS*DD);
    tgemm<0,0,0><<<dim3(BB*SS/128, (VV + 255)/256), 256, TG_SMEM>>>(pAh, pAl, pVh, pVl,
                                                                    0, 0, logits, BB*SS, VV, DD, VV);

    loss_row_kernel<<<BB*(SS-1), 256>>>(logits, labels);
    loss_final_kernel<<<1, 256>>>(out);
}

// round 16
// speedup vs baseline: 1.1459x; 1.1459x over previous
#include <cuda_runtime.h>
#include <cuda_bf16.h>
#include <mma.h>
#include <stdint.h>
#include <math.h>

using namespace nvcuda;

#define BB 4
#define SS 512
#define VV 50257
#define DD 768
#define HH 12
#define DHH 64
#define NLAYER 2
#define DFFN 3072
#define LAT_START 64
#define NLAT 6
#define ATT_SCALE 0.125f

#define WQKV_T_OFF 0
#define WO_T_OFF   (2304*768)
#define W1_T_OFF   (2304*768 + 768*768)
#define W2_T_OFF   (2304*768 + 768*768 + 3072*768)
#define PER_L      (2304*768 + 768*768 + 3072*768 + 768*3072)
#define TG_SMEM    81920
#define LDS_A 40
#define ABUF (128*LDS_A)

static __device__ float g_embeds[BB*SS*DD];
static __device__ float g_X   [BB*SS*DD];
static __device__ float g_H   [BB*SS*DD];
static __device__ float g_HID [BB*SS*DD];
static __device__ float g_QKV [BB*SS*3*DD];
static __device__ float g_CTX [BB*SS*DD];
static __device__ float g_G   [BB*SS*DFFN];
static __device__ float g_K   [NLAYER*BB*HH*SS*DHH];
static __device__ float g_V   [NLAYER*BB*HH*SS*DHH];
static __device__ float g_part[24*4*DFFN];
static __device__ float g_nll [BB*(SS-1)];
static __device__ __align__(16) __nv_bfloat16 g_Whi[2*PER_L];
static __device__ __align__(16) __nv_bfloat16 g_Wlo[2*PER_L];
static __device__ __align__(16) __nv_bfloat16 g_Vhi[(size_t)VV*DD];
static __device__ __align__(16) __nv_bfloat16 g_Vlo[(size_t)VV*DD];
static __device__ __align__(16) __nv_bfloat16 g_Ahi[BB*SS*DFFN];
static __device__ __align__(16) __nv_bfloat16 g_Alo[BB*SS*DFFN];

__device__ __forceinline__ float wrsum(float v) {
    #pragma unroll
    for (int o = 16; o; o >>= 1) v += __shfl_xor_sync(0xffffffffu, v, o);
    return v;
}
__device__ __forceinline__ float wrmax(float v) {
    #pragma unroll
    for (int o = 16; o; o >>= 1) v = fmaxf(v, __shfl_xor_sync(0xffffffffu, v, o));
    return v;
}
__device__ __forceinline__ float gelu_tanh(float u) {
    return 0.5f*u*(1.f + tanhf(0.7978845608028654f*(u + 0.044715f*u*u*u)));
}
// polynomial exp (FMA pipe, no MUFU); rel err ~2e-6; valid for d <= ~0
__device__ __forceinline__ float fexp(float d) {
    float t = d * 1.4426950408889634f;
    t = fmaxf(t, -127.0f);
    float fi = rintf(t);
    float f = t - fi;
    int i = (int)fi;
    float p = 0.0013333558f;
    p = fmaf(p, f, 0.0096181291f);
    p = fmaf(p, f, 0.0555041087f);
    p = fmaf(p, f, 0.2402265069f);
    p = fmaf(p, f, 0.6931471806f);
    p = fmaf(p, f, 1.0f);
    float sc = __int_as_float((i + 127) << 23);
    return p * sc;
}

__global__ void cvt_split(const float* __restrict__ s, __nv_bfloat16* __restrict__ hi,
                          __nv_bfloat16* __restrict__ lo, int n) {
    int i = blockIdx.x * 256 + threadIdx.x;
    if (i >= n) return;
    float v = s[i];
    __nv_bfloat16 h = __float2bfloat16(v);
    hi[i] = h;
    lo[i] = __float2bfloat16(v - __bfloat162float(h));
}

__global__ void cvt_tr(const float* __restrict__ W, __nv_bfloat16* __restrict__ hiT,
                       __nv_bfloat16* __restrict__ loT, int K, int N) {
    __shared__ float t[32][33];
    int k0 = blockIdx.y * 32, n0 = blockIdx.x * 32;
    for (int i = threadIdx.y; i < 32; i += 8)
        t[i][threadIdx.x] = W[(size_t)(k0 + i)*N + n0 + threadIdx.x];
    __syncthreads();
    for (int i = threadIdx.y; i < 32; i += 8) {
        int n = n0 + i, k = k0 + threadIdx.x;
        float v = t[threadIdx.x][i];
        __nv_bfloat16 h = __float2bfloat16(v);
        hiT[(size_t)n*K + k] = h;
        loT[(size_t)n*K + k] = __float2bfloat16(v - __bfloat162float(h));
    }
}

// HMMA (wmma bf16) split-bf16 GEMM — R14 configuration (measured 5879us).
// C[M,N]=epi(A x B^T). B is [N,K] row-major.
// Tile 128x128, 8 warps of 64x32, K chunks of 32, double-buffered.
template<int ACT, int HASRES, int HASBIAS>
__global__ void __launch_bounds__(256, 1)
tgemm(const __nv_bfloat16* __restrict__ Ah, const __nv_bfloat16* __restrict__ Al,
      const __nv_bfloat16* __restrict__ Bh, const __nv_bfloat16* __restrict__ Bl,
      const float* __restrict__ bias, const float* __restrict__ res,
      float* __restrict__ C, int M, int N, int K, int ldc) {
    extern __shared__ __align__(16) __nv_bfloat16 smem[];
    int tid = threadIdx.x, wid = tid >> 5, lane = tid & 31;
    int row0 = blockIdx.x * 128, col0 = blockIdx.y * 128;
    int wm = wid >> 2, wn = wid & 3;        // warp tile: rows wm*64, cols wn*32

    wmma::fragment<wmma::accumulator, 16, 16, 16, float> acc[4][2];
    #pragma unroll
    for (int m = 0; m < 4; m++)
        #pragma unroll
        for (int n = 0; n < 2; n++) wmma::fill_fragment(acc[m][n], 0.0f);

    int KC = K >> 5;

    // preload chunk 0 into buffer 0
    {
        int kc = 0, b = 0;
        for (int i = tid; i < 1024; i += 256) {   // A hi|lo: 2 x 128 x 32
            int var = i >> 9, e = i & 511, r = e >> 2, g = e & 3;
            int gr = row0 + r;
            uint4 v = make_uint4(0,0,0,0);
            const __nv_bfloat16* s = var ? Al : Ah;
            if (gr < M) v = *(const uint4*)(s + (size_t)gr*K + kc*32 + g*8);
            *(uint4*)(smem + b*4*ABUF + var*ABUF + r*LDS_A + g*8) = v;
        }
        for (int i = tid; i < 1024; i += 256) {   // B hi|lo
            int var = i >> 9, e = i & 511, r = e >> 2, g = e & 3;
            int gn = col0 + r;
            uint4 v = make_uint4(0,0,0,0);
            const __nv_bfloat16* s = var ? Bl : Bh;
            if (gn < N) v = *(const uint4*)(s + (size_t)gn*K + kc*32 + g*8);
            *(uint4*)(smem + b*4*ABUF + (2 + var)*ABUF + r*LDS_A + g*8) = v;
        }
    }
    __syncthreads();

    for (int kc = 0; kc < KC; kc++) {
        int b = kc & 1;
        // prefetch next chunk into regs
        uint4 pa[4], pb[4];
        if (kc + 1 < KC) {
            #pragma unroll
            for (int j = 0; j < 4; j++) {
                int i = tid + j*256;
                int var = i >> 9, e = i & 511, r = e >> 2, g = e & 3;
                int gr = row0 + r;
                pa[j] = make_uint4(0,0,0,0);
                const __nv_bfloat16* s = var ? Al : Ah;
                if (gr < M) pa[j] = *(const uint4*)(s + (size_t)gr*K + (kc+1)*32 + g*8);
                int gn = col0 + r;
                pb[j] = make_uint4(0,0,0,0);
                const __nv_bfloat16* s2 = var ? Bl : Bh;
                if (gn < N) pb[j] = *(const uint4*)(s2 + (size_t)gn*K + (kc+1)*32 + g*8);
            }
        }

        const __nv_bfloat16* bufp = smem + b*4*ABUF;
        #pragma unroll
        for (int ks = 0; ks < 2; ks++) {
            wmma::fragment<wmma::matrix_b, 16, 16, 16, __nv_bfloat16, wmma::col_major> fbh[2], fbl[2];
            #pragma unroll
            for (int n = 0; n < 2; n++) {
                const __nv_bfloat16* pBh = bufp + 2*ABUF + (wn*32 + n*16)*LDS_A + ks*16;
                const __nv_bfloat16* pBl = bufp + 3*ABUF + (wn*32 + n*16)*LDS_A + ks*16;
                wmma::load_matrix_sync(fbh[n], pBh, LDS_A);
                wmma::load_matrix_sync(fbl[n], pBl, LDS_A);
            }
            #pragma unroll
            for (int m = 0; m < 4; m++) {
                wmma::fragment<wmma::matrix_a, 16, 16, 16, __nv_bfloat16, wmma::row_major> fah, fal;
                const __nv_bfloat16* pAh = bufp + 0*ABUF + (wm*64 + m*16)*LDS_A + ks*16;
                const __nv_bfloat16* pAl = bufp + 1*ABUF + (wm*64 + m*16)*LDS_A + ks*16;
                wmma::load_matrix_sync(fah, pAh, LDS_A);
                wmma::load_matrix_sync(fal, pAl, LDS_A);
                #pragma unroll
                for (int n = 0; n < 2; n++) {
                    wmma::mma_sync(acc[m][n], fah, fbh[n], acc[m][n]);
                    wmma::mma_sync(acc[m][n], fah, fbl[n], acc[m][n]);
                    wmma::mma_sync(acc[m][n], fal, fbh[n], acc[m][n]);
                }
            }
        }

        if (kc + 1 < KC) {
            int nb = (kc + 1) & 1;
            #pragma unroll
            for (int j = 0; j < 4; j++) {
                int i = tid + j*256;
                int var = i >> 9, e = i & 511, r = e >> 2, g = e & 3;
                *(uint4*)(smem + nb*4*ABUF + var*ABUF + r*LDS_A + g*8) = pa[j];
                *(uint4*)(smem + nb*4*ABUF + (2 + var)*ABUF + r*LDS_A + g*8) = pb[j];
            }
        }
        __syncthreads();
    }

    // epilogue: store accs to smem (float, stride 36), then fused writes
    float* fsm = (float*)smem;
    float* wsm = fsm + wid * (64*36);
    #pragma unroll
    for (int m = 0; m < 4; m++)
        #pragma unroll
        for (int n = 0; n < 2; n++)
            wmma::store_matrix_sync(wsm + m*16*36 + n*16, acc[m][n], 36, wmma::mem_row_major);
    __syncwarp();
    int cc = lane;
    int gc = col0 + wn*32 + cc;
    if (gc < N) {
        float bv = HASBIAS ? bias[gc] : 0.f;
        for (int rr = 0; rr < 64; rr++) {
            int gr = row0 + wm*64 + rr;
            if (gr >= M) break;
            float v = wsm[rr*36 + cc];
            if (HASBIAS) v += bv;
            if (ACT)     v = gelu_tanh(v);
            if (HASRES)  v += res[(size_t)gr*ldc + gc];
            C[(size_t)gr*ldc + gc] = v;
        }
    }
}

__global__ void embed_init_kernel(const int* __restrict__ ids, const float* __restrict__ wte) {
    int idx = blockIdx.x * 256 + threadIdx.x;
    if (idx >= BB*SS*DD) return;
    int r = idx / DD, d = idx - r*DD;
    g_embeds[idx] = wte[(size_t)ids[r]*DD + d];
}
__global__ void build_x_kernel(const int* __restrict__ pos_ids, const float* __restrict__ wpe,
                               int qs, int qc) {
    int idx = blockIdx.x * 256 + threadIdx.x;
    if (idx >= BB*qc*DD) return;
    int r = idx / DD, d = idx - r*DD;
    int b = r / qc, t = r - b*qc;
    int s = qs + t;
    g_X[idx] = g_embeds[((size_t)b*SS + s)*DD + d] + wpe[(size_t)pos_ids[b*SS + s]*DD + d];
}
__global__ void ln_kernel(const float* __restrict__ in, float* __restrict__ out,
                          const float* __restrict__ gam, const float* __restrict__ bet,
                          int qc, int qs, int scatter) {
    int r = blockIdx.x;
    const float* x = in + (size_t)r*DD;
    int tid = threadIdx.x;
    float x0 = x[tid], x1 = x[tid+256], x2 = x[tid+512];
    __shared__ float sh[8];
    float s = wrsum(x0 + x1 + x2);
    if ((tid & 31) == 0) sh[tid >> 5] = s;
    __syncthreads();
    if (tid == 0) { float t = 0.f; for (int i = 0; i < 8; i++) t += sh[i]; sh[0] = t * (1.f/DD); }
    __syncthreads();
    float mean = sh[0];
    float d0 = x0 - mean, d1 = x1 - mean, d2 = x2 - mean;
    __syncthreads();
    float q = wrsum(d0*d0 + d1*d1 + d2*d2);
    if ((tid & 31) == 0) sh[tid >> 5] = q;
    __syncthreads();
    if (tid == 0) { float t = 0.f; for (int i = 0; i < 8; i++) t += sh[i]; sh[0] = rsqrtf(t*(1.f/DD) + 1e-5f); }
    __syncthreads();
    float rstd = sh[0];
    int orow = r;
    if (scatter) { int b = r / qc, t = r - b*qc; orow = b*SS + qs + t; }
    float* o = out + (size_t)orow*DD;
    o[tid]     = d0*rstd*gam[tid]     + bet[tid];
    o[tid+256] = d1*rstd*gam[tid+256] + bet[tid+256];
    o[tid+512] = d2*rstd*gam[tid+512] + bet[tid+512];
}

__global__ void gemv4_part(const float* __restrict__ A, const float* __restrict__ W, int N, int K) {
    __shared__ float Ash[4][128];
    int tid = threadIdx.x;
    int k0 = blockIdx.y * 128;
    for (int i = tid; i < 512; i += 128) {
        int r = i >> 7, k = i & 127;
        Ash[r][k] = A[(size_t)r*K + k0 + k];
    }
    __syncthreads();
    int n = blockIdx.x * 128 + tid;
    const float* wp = W + (size_t)k0*N + n;
    float s0=0.f, s1=0.f, s2=0.f, s3=0.f;
    #pragma unroll 8
    for (int k = 0; k < 128; k++) {
        float w = wp[(size_t)k*N];
        s0 = fmaf(w, Ash[0][k], s0);
        s1 = fmaf(w, Ash[1][k], s1);
        s2 = fmaf(w, Ash[2][k], s2);
        s3 = fmaf(w, Ash[3][k], s3);
    }
    float* pp = g_part + (size_t)blockIdx.y*4*DFFN + n;
    pp[0] = s0; pp[DFFN] = s1; pp[2*DFFN] = s2; pp[3*DFFN] = s3;
}
template<int ACT, int HASRES>
__global__ void gemv4_red(const float* __restrict__ bias, const float* __restrict__ res,
                          float* __restrict__ C, int N, int kch) {
    int n = blockIdx.x * 256 + threadIdx.x;
    if (n >= N) return;
    #pragma unroll
    for (int r = 0; r < 4; r++) {
        float s = bias[n];
        for (int c = 0; c < kch; c++) s += g_part[(size_t)c*4*DFFN + r*DFFN + n];
        if (ACT)    s = gelu_tanh(s);
        if (HASRES) s += res[(size_t)r*N + n];
        C[(size_t)r*N + n] = s;
    }
}

__global__ void kv_scatter(int l, int qs, int qc) {
    int idx = blockIdx.x * 256 + threadIdx.x;
    if (idx >= BB*qc*DD) return;
    int r = idx / DD, d = idx - r*DD;
    int b = r / qc, t = r - b*qc;
    int h = d >> 6, dh = d & 63;
    size_t c = ((size_t)((l*BB + b)*HH + h)*SS + qs + t)*DHH + dh;
    g_K[c] = g_QKV[(size_t)r*(3*DD) + DD   + d];
    g_V[c] = g_QKV[(size_t)r*(3*DD) + 2*DD + d];
}

__global__ void attn_kernel(int l, int qs, int qc, const int* __restrict__ amask) {
    __shared__ float qsh[8][4][64];
    int w = threadIdx.x >> 5, lane = threadIdx.x & 31;
    int nqt = (qc + 3) >> 2;
    int gw = blockIdx.x * 8 + w;
    if (gw >= nqt * BB * HH) return;
    int h = gw % HH, r1 = gw / HH, b = r1 % BB, qt = r1 / BB;
    int t0 = qt * 4;
    #pragma unroll
    for (int i = 0; i < 4; i++) {
        int t = t0 + i; if (t >= qc) t = qc - 1;
        const float* qp = g_QKV + (size_t)(b*qc + t)*(3*DD) + h*DHH;
        qsh[w][i][lane]      = qp[lane]      * ATT_SCALE;
        qsh[w][i][lane + 32] = qp[lane + 32] * ATT_SCALE;
    }
    __syncwarp();
    int qlast = min(t0 + 3, qc - 1);
    int qmax = qs + qlast;
    const float* kc = g_K + (size_t)((l*BB + b)*HH + h)*SS*DHH;
    const float* vc = g_V + (size_t)((l*BB + b)*HH + h)*SS*DHH;
    float m0=-1e30f,m1=-1e30f,m2=-1e30f,m3=-1e30f, dn0=0.f,dn1=0.f,dn2=0.f,dn3=0.f;
    float2 a0={0.f,0.f},a1={0.f,0.f},a2={0.f,0.f},a3={0.f,0.f};
    for (int j0 = 0; j0 <= qmax; j0 += 32) {
        int j = j0 + lane;
        float s0=-1e30f,s1=-1e30f,s2=-1e30f,s3=-1e30f;
        if (j <= qmax && amask[b*SS + j] != 0) {
            const float4* kr = (const float4*)(kc + (size_t)j*DHH);
            float u0=0.f,u1=0.f,u2=0.f,u3=0.f;
            #pragma unroll
            for (int i2 = 0; i2 < 16; i2++) {
                float4 kv = kr[i2];
                float4 q0 = *(const float4*)&qsh[w][0][i2*4];
                float4 q1 = *(const float4*)&qsh[w][1][i2*4];
                float4 q2 = *(const float4*)&qsh[w][2][i2*4];
                float4 q3 = *(const float4*)&qsh[w][3][i2*4];
                u0 += kv.x*q0.x + kv.y*q0.y + kv.z*q0.z + kv.w*q0.w;
                u1 += kv.x*q1.x + kv.y*q1.y + kv.z*q1.z + kv.w*q1.w;
                u2 += kv.x*q2.x + kv.y*q2.y + kv.z*q2.z + kv.w*q2.w;
                u3 += kv.x*q3.x + kv.y*q3.y + kv.z*q3.z + kv.w*q3.w;
            }
            s0 = (j <= qs + t0    ) ? u0 : -1e30f;
            s1 = (j <= qs + t0 + 1) ? u1 : -1e30f;
            s2 = (j <= qs + t0 + 2) ? u2 : -1e30f;
            s3 = (j <= qs + t0 + 3) ? u3 : -1e30f;
        }
        float n0 = fmaxf(m0, wrmax(s0)), n1 = fmaxf(m1, wrmax(s1));
        float n2 = fmaxf(m2, wrmax(s2)), n3 = fmaxf(m3, wrmax(s3));
        float p0 = __expf(s0-n0), p1 = __expf(s1-n1), p2 = __expf(s2-n2), p3 = __expf(s3-n3);
        float q0 = wrsum(p0), q1 = wrsum(p1), q2 = wrsum(p2), q3 = wrsum(p3);
        float e0 = __expf(m0-n0), e1 = __expf(m1-n1), e2 = __expf(m2-n2), e3 = __expf(m3-n3);
        dn0 = dn0*e0 + q0; a0.x *= e0; a0.y *= e0; m0 = n0;
        dn1 = dn1*e1 + q1; a1.x *= e1; a1.y *= e1; m1 = n1;
        dn2 = dn2*e2 + q2; a2.x *= e2; a2.y *= e2; m2 = n2;
        dn3 = dn3*e3 + q3; a3.x *= e3; a3.y *= e3; m3 = n3;
        int jc = min(32, qmax - j0 + 1);
        for (int jj = 0; jj < jc; jj++) {
            float2 vv = *(const float2*)(vc + (size_t)(j0 + jj)*DHH + lane*2);
            float w0 = __shfl_sync(0xffffffffu, p0, jj), w1 = __shfl_sync(0xffffffffu, p1, jj);
            float w2 = __shfl_sync(0xffffffffu, p2, jj), w3 = __shfl_sync(0xffffffffu, p3, jj);
            a0.x = fmaf(w0, vv.x, a0.x); a0.y = fmaf(w0, vv.y, a0.y);
            a1.x = fmaf(w1, vv.x, a1.x); a1.y = fmaf(w1, vv.y, a1.y);
            a2.x = fmaf(w2, vv.x, a2.x); a2.y = fmaf(w2, vv.y, a2.y);
            a3.x = fmaf(w3, vv.x, a3.x); a3.y = fmaf(w3, vv.y, a3.y);
        }
    }
    float2 ac[4] = {a0,a1,a2,a3};
    float dn[4] = {dn0,dn1,dn2,dn3};
    #pragma unroll
    for (int i = 0; i < 4; i++) {
        int t = t0 + i;
        if (t < qc) {
            float inv = 1.f / dn[i];
            *(float2*)&g_CTX[(size_t)(b*qc + t)*DD + h*DHH + lane*2] =
                make_float2(ac[i].x*inv, ac[i].y*inv);
        }
    }
}

__global__ void latent_update_kernel(int slot) {
    int idx = blockIdx.x * 256 + threadIdx.x;
    if (idx >= BB*DD) return;
    int b = idx / DD, d = idx - b*DD;
    g_embeds[((size_t)b*SS + slot)*DD + d] = g_HID[((size_t)b*SS + slot - 1)*DD + d];
}

// single-pass online-softmax NLL (poly exp on FMA pipe, one logits read)
__global__ void loss_row_kernel(const float* __restrict__ logits, const int* __restrict__ labels) {
    int r = blockIdx.x;
    int b = r / (SS-1), t = r - b*(SS-1);
    const float* x = logits + ((size_t)(b*SS + t))*VV;
    int tid = threadIdx.x;
    float mx = -1e30f, s = 0.f;
    for (int i = tid; i < VV; i += 256) {
        float v = x[i];
        float nm = fmaxf(mx, v);
        s = s * fexp(mx - nm) + fexp(v - nm);
        mx = nm;
    }
    #pragma unroll
    for (int o = 16; o; o >>= 1) {
        float om = __shfl_xor_sync(0xffffffffu, mx, o);
        float os = __shfl_xor_sync(0xffffffffu, s, o);
        float nm = fmaxf(mx, om);
        s = s * fexp(mx - nm) + os * fexp(om - nm);
        mx = nm;
    }
    __shared__ float shm[8], shs[8];
    if ((tid & 31) == 0) { shm[tid >> 5] = mx; shs[tid >> 5] = s; }
    __syncthreads();
    if (tid == 0) {
        float M2 = shm[0], S2 = shs[0];
        for (int i = 1; i < 8; i++) {
            float nm = fmaxf(M2, shm[i]);
            S2 = S2 * fexp(M2 - nm) + shs[i] * fexp(shm[i] - nm);
            M2 = nm;
        }
        g_nll[r] = logf(S2) + M2 - x[labels[b*SS + t + 1]];
    }
}
__global__ void loss_final_kernel(float* out) {
    int tid = threadIdx.x;
    __shared__ float sh[8];
    float s = 0.f;
    for (int i = tid; i < BB*(SS-1); i += 256) s += g_nll[i];
    s = wrsum(s);
    if ((tid & 31) == 0) sh[tid >> 5] = s;
    __syncthreads();
    if (tid == 0) {
        float t = 0.f; for (int i = 0; i < 8; i++) t += sh[i];
        out[0] = t / (float)(BB*(SS-1));
    }
}

extern "C" void kernel_launch(void* const* d_in, const int* in_sizes, int n_in,
                              void* d_out, int out_size) {
    const int*   input_ids = (const int*)d_in[0];
    const int*   amask     = (const int*)d_in[1];
    const int*   labels    = (const int*)d_in[2];
    const int*   pos_ids   = (const int*)d_in[3];
    const float* wte   = (const float*)d_in[4];
    const float* wpe   = (const float*)d_in[5];
    const float* ln1_g = (const float*)d_in[6];
    const float* ln1_b = (const float*)d_in[7];
    const float* Wqkv  = (const float*)d_in[8];
    const float* bqkv  = (const float*)d_in[9];
    const float* Wo    = (const float*)d_in[10];
    const float* bo    = (const float*)d_in[11];
    const float* ln2_g = (const float*)d_in[12];
    const float* ln2_b = (const float*)d_in[13];
    const float* W1    = (const float*)d_in[14];
    const float* b1    = (const float*)d_in[15];
    const float* W2    = (const float*)d_in[16];
    const float* b2    = (const float*)d_in[17];
    const float* lnf_g = (const float*)d_in[18];
    const float* lnf_b = (const float*)d_in[19];

    float* out    = (float*)d_out;
    float* logits = out + 1;

    cudaFuncSetAttribute(tgemm<0,0,0>, cudaFuncAttributeMaxDynamicSharedMemorySize, TG_SMEM);
    cudaFuncSetAttribute(tgemm<0,0,1>, cudaFuncAttributeMaxDynamicSharedMemorySize, TG_SMEM);
    cudaFuncSetAttribute(tgemm<0,1,1>, cudaFuncAttributeMaxDynamicSharedMemorySize, TG_SMEM);
    cudaFuncSetAttribute(tgemm<1,0,1>, cudaFuncAttributeMaxDynamicSharedMemorySize, TG_SMEM);

    float *pX, *pH, *pHID, *pQKV, *pCTX, *pG;
    cudaGetSymbolAddress((void**)&pX,   g_X);
    cudaGetSymbolAddress((void**)&pH,   g_H);
    cudaGetSymbolAddress((void**)&pHID, g_HID);
    cudaGetSymbolAddress((void**)&pQKV, g_QKV);
    cudaGetSymbolAddress((void**)&pCTX, g_CTX);
    cudaGetSymbolAddress((void**)&pG,   g_G);
    __nv_bfloat16 *pAh, *pAl, *pWh, *pWl, *pVh, *pVl;
    cudaGetSymbolAddress((void**)&pAh, g_Ahi);
    cudaGetSymbolAddress((void**)&pAl, g_Alo);
    cudaGetSymbolAddress((void**)&pWh, g_Whi);
    cudaGetSymbolAddress((void**)&pWl, g_Wlo);
    cudaGetSymbolAddress((void**)&pVh, g_Vhi);
    cudaGetSymbolAddress((void**)&pVl, g_Vlo);

    embed_init_kernel<<<(BB*SS*DD + 255)/256, 256>>>(input_ids, wte);
    cvt_split<<<(VV*DD + 255)/256, 256>>>(wte, pVh, pVl, VV*DD);
    for (int l = 0; l < NLAYER; l++) {
        __nv_bfloat16* wh = pWh + (size_t)l*PER_L;
        __nv_bfloat16* wl = pWl + (size_t)l*PER_L;
        cvt_tr<<<dim3(2304/32, 768/32),  dim3(32,8)>>>(Wqkv + (size_t)l*DD*3*DD, wh + WQKV_T_OFF, wl + WQKV_T_OFF, 768, 2304);
        cvt_tr<<<dim3(768/32,  768/32),  dim3(32,8)>>>(Wo   + (size_t)l*DD*DD,   wh + WO_T_OFF,   wl + WO_T_OFF,   768, 768);
        cvt_tr<<<dim3(3072/32, 768/32),  dim3(32,8)>>>(W1   + (size_t)l*DD*DFFN, wh + W1_T_OFF,   wl + W1_T_OFF,   768, 3072);
        cvt_tr<<<dim3(768/32,  3072/32), dim3(32,8)>>>(W2   + (size_t)l*DFFN*DD, wh + W2_T_OFF,   wl + W2_T_OFF,   3072, 768);
    }

    const int QS[7] = {0, 64, 65, 66, 67, 68, 69};
    const int QC[7] = {64, 1,  1,  1,  1,  1,  SS - 69};

    for (int p = 0; p < 7; p++) {
        int qs = QS[p], qc = QC[p];
        int M = BB * qc;
        int mt = (M + 127)/128;

        build_x_kernel<<<(M*DD + 255)/256, 256>>>(pos_ids, wpe, qs, qc);

        for (int l = 0; l < NLAYER; l++) {
            __nv_bfloat16* wh = pWh + (size_t)l*PER_L;
            __nv_bfloat16* wl = pWl + (size_t)l*PER_L;
            const float* Wq  = Wqkv + (size_t)l*DD*3*DD;  const float* bq  = bqkv + (size_t)l*3*DD;
            const float* Wol = Wo   + (size_t)l*DD*DD;    const float* bol = bo   + (size_t)l*DD;
            const float* W1l = W1   + (size_t)l*DD*DFFN;  const float* b1l = b1   + (size_t)l*DFFN;
            const float* W2l = W2   + (size_t)l*DFFN*DD;  const float* b2l = b2   + (size_t)l*DD;

            ln_kernel<<<M, 256>>>(pX, pH, ln1_g + l*DD, ln1_b + l*DD, qc, qs, 0);

            if (qc == 1) {
                gemv4_part<<<dim3(3*DD/128, DD/128), 128>>>(pH, Wq, 3*DD, DD);
                gemv4_red<0,0><<<(3*DD + 255)/256, 256>>>(bq, 0, pQKV, 3*DD, DD/128);
            } else {
                cvt_split<<<(M*DD + 255)/256, 256>>>(pH, pAh, pAl, M*DD);
                tgemm<0,0,1><<<dim3(mt, 18), 256, TG_SMEM>>>(pAh, pAl, wh + WQKV_T_OFF, wl + WQKV_T_OFF,
                                                             bq, 0, pQKV, M, 3*DD, DD, 3*DD);
            }

            kv_scatter<<<(M*DD + 255)/256, 256>>>(l, qs, qc);
            attn_kernel<<<(((qc+3)/4)*BB*HH + 7)/8, 256>>>(l, qs, qc, amask);

            if (qc == 1) {
                gemv4_part<<<dim3(DD/128, DD/128), 128>>>(pCTX, Wol, DD, DD);
                gemv4_red<0,1><<<(DD + 255)/256, 256>>>(bol, pX, pX, DD, DD/128);
            } else {
                cvt_split<<<(M*DD + 255)/256, 256>>>(pCTX, pAh, pAl, M*DD);
                tgemm<0,1,1><<<dim3(mt, 6), 256, TG_SMEM>>>(pAh, pAl, wh + WO_T_OFF, wl + WO_T_OFF,
                                                            bol, pX, pX, M, DD, DD, DD);
            }

            ln_kernel<<<M, 256>>>(pX, pH, ln2_g + l*DD, ln2_b + l*DD, qc, qs, 0);

            if (qc == 1) {
                gemv4_part<<<dim3(DFFN/128, DD/128), 128>>>(pH, W1l, DFFN, DD);
                gemv4_red<1,0><<<(DFFN + 255)/256, 256>>>(b1l, 0, pG, DFFN, DD/128);
                gemv4_part<<<dim3(DD/128, DFFN/128), 128>>>(pG, W2l, DD, DFFN);
                gemv4_red<0,1><<<(DD + 255)/256, 256>>>(b2l, pX, pX, DD, DFFN/128);
            } else {
                cvt_split<<<(M*DD + 255)/256, 256>>>(pH, pAh, pAl, M*DD);
                tgemm<1,0,1><<<dim3(mt, 24), 256, TG_SMEM>>>(pAh, pAl, wh + W1_T_OFF, wl + W1_T_OFF,
                                                             b1l, 0, pG, M, DFFN, DD, DFFN);
                cvt_split<<<(M*DFFN + 255)/256, 256>>>(pG, pAh, pAl, M*DFFN);
                tgemm<0,1,1><<<dim3(mt, 6), 256, TG_SMEM>>>(pAh, pAl, wh + W2_T_OFF, wl + W2_T_OFF,
                                                            b2l, pX, pX, M, DD, DFFN, DD);
            }
        }

        ln_kernel<<<M, 256>>>(pX, pHID, lnf_g, lnf_b, qc, qs, 1);

        if (p < NLAT) latent_update_kernel<<<(BB*DD + 255)/256, 256>>>(LAT_START + p);
    }

    cvt_split<<<(BB*SS*DD + 255)/256, 256>>>(pHID, pAh, pAl, BB*SS*DD);
    tgemm<0,0,0><<<dim3(BB*SS/128, (VV + 127)/128), 256, TG_SMEM>>>(pAh, pAl, pVh, pVl,
                                                                    0, 0, logits, BB*SS, VV, DD, VV);

    loss_row_kernel<<<BB*(SS-1), 256>>>(logits, labels);
    loss_final_kernel<<<1, 256>>>(out);
}

// round 17
// speedup vs baseline: 1.6306x; 1.4229x over previous
#include <cuda_runtime.h>
#include <cuda_fp16.h>
#include <mma.h>
#include <stdint.h>
#include <math.h>

using namespace nvcuda;

#define BB 4
#define SS 512
#define VV 50257
#define DD 768
#define HH 12
#define DHH 64
#define NLAYER 2
#define DFFN 3072
#define LAT_START 64
#define NLAT 6
#define ATT_SCALE 0.125f

#define WQKV_T_OFF 0
#define WO_T_OFF   (2304*768)
#define W1_T_OFF   (2304*768 + 768*768)
#define W2_T_OFF   (2304*768 + 768*768 + 3072*768)
#define PER_L      (2304*768 + 768*768 + 3072*768 + 768*3072)
#define TG_SMEM    73728
#define LDS_A 40
#define ABUF (128*LDS_A)

static __device__ float g_embeds[BB*SS*DD];
static __device__ float g_X   [BB*SS*DD];
static __device__ float g_H   [BB*SS*DD];
static __device__ float g_HID [BB*SS*DD];
static __device__ float g_QKV [BB*SS*3*DD];
static __device__ float g_CTX [BB*SS*DD];
static __device__ float g_G   [BB*SS*DFFN];
static __device__ float g_K   [NLAYER*BB*HH*SS*DHH];
static __device__ float g_V   [NLAYER*BB*HH*SS*DHH];
static __device__ float g_part[24*4*DFFN];
static __device__ float g_nll [BB*(SS-1)];
static __device__ __align__(16) __half g_Whi[2*PER_L];
static __device__ __align__(16) __half g_Wlo[2*PER_L];
static __device__ __align__(16) __half g_Vhi[(size_t)VV*DD];
static __device__ __align__(16) __half g_Vlo[(size_t)VV*DD];
static __device__ __align__(16) __half g_Act[BB*SS*DFFN];

__device__ __forceinline__ float wrsum(float v) {
    #pragma unroll
    for (int o = 16; o; o >>= 1) v += __shfl_xor_sync(0xffffffffu, v, o);
    return v;
}
__device__ __forceinline__ float wrmax(float v) {
    #pragma unroll
    for (int o = 16; o; o >>= 1) v = fmaxf(v, __shfl_xor_sync(0xffffffffu, v, o));
    return v;
}
__device__ __forceinline__ float gelu_tanh(float u) {
    return 0.5f*u*(1.f + tanhf(0.7978845608028654f*(u + 0.044715f*u*u*u)));
}
// polynomial exp (FMA pipe); rel err ~2e-6; valid for d <= ~0
__device__ __forceinline__ float fexp(float d) {
    float t = d * 1.4426950408889634f;
    t = fmaxf(t, -127.0f);
    float fi = rintf(t);
    float f = t - fi;
    int i = (int)fi;
    float p = 0.0013333558f;
    p = fmaf(p, f, 0.0096181291f);
    p = fmaf(p, f, 0.0555041087f);
    p = fmaf(p, f, 0.2402265069f);
    p = fmaf(p, f, 0.6931471806f);
    p = fmaf(p, f, 1.0f);
    float sc = __int_as_float((i + 127) << 23);
    return p * sc;
}

// activations -> single fp16
__global__ void cvt_half(const float* __restrict__ s, __half* __restrict__ o, int n) {
    int i = blockIdx.x * 256 + threadIdx.x;
    if (i >= n) return;
    o[i] = __float2half(s[i]);
}
// weights (already [N,K]) -> fp16 hi + lo
__global__ void cvt_split_h(const float* __restrict__ s, __half* __restrict__ hi,
                            __half* __restrict__ lo, int n) {
    int i = blockIdx.x * 256 + threadIdx.x;
    if (i >= n) return;
    float v = s[i];
    __half h = __float2half(v);
    hi[i] = h;
    lo[i] = __float2half(v - __half2float(h));
}
// W [K,N] fp32 -> WT [N,K] fp16 hi + lo
__global__ void cvt_tr_h(const float* __restrict__ W, __half* __restrict__ hiT,
                         __half* __restrict__ loT, int K, int N) {
    __shared__ float t[32][33];
    int k0 = blockIdx.y * 32, n0 = blockIdx.x * 32;
    for (int i = threadIdx.y; i < 32; i += 8)
        t[i][threadIdx.x] = W[(size_t)(k0 + i)*N + n0 + threadIdx.x];
    __syncthreads();
    for (int i = threadIdx.y; i < 32; i += 8) {
        int n = n0 + i, k = k0 + threadIdx.x;
        float v = t[threadIdx.x][i];
        __half h = __float2half(v);
        hiT[(size_t)n*K + k] = h;
        loT[(size_t)n*K + k] = __float2half(v - __half2float(h));
    }
}

// HMMA split-fp16 GEMM (2 terms: A*Wh + A*Wl). C[M,N]=epi(A x B^T). B is [N,K] row-major.
// Tile 128x128, 8 warps of 64x32, K chunks of 32, double-buffered.
template<int ACT, int HASRES, int HASBIAS>
__global__ void __launch_bounds__(256, 1)
tgemm(const __half* __restrict__ A,
      const __half* __restrict__ Bh, const __half* __restrict__ Bl,
      const float* __restrict__ bias, const float* __restrict__ res,
      float* __restrict__ C, int M, int N, int K, int ldc) {
    extern __shared__ __align__(16) __half smem[];
    int tid = threadIdx.x, wid = tid >> 5, lane = tid & 31;
    int row0 = blockIdx.x * 128, col0 = blockIdx.y * 128;
    int wm = wid >> 2, wn = wid & 3;        // warp tile: rows wm*64, cols wn*32

    wmma::fragment<wmma::accumulator, 16, 16, 16, float> acc[4][2];
    #pragma unroll
    for (int m = 0; m < 4; m++)
        #pragma unroll
        for (int n = 0; n < 2; n++) wmma::fill_fragment(acc[m][n], 0.0f);

    int KC = K >> 5;

    // preload chunk 0 into buffer 0: A (512 uint4) + Bh|Bl (1024 uint4)
    for (int i = tid; i < 1536; i += 256) {
        uint4 v = make_uint4(0,0,0,0);
        __half* dst;
        if (i < 512) {
            int r = i >> 2, g = i & 3;
            int gr = row0 + r;
            if (gr < M) v = *(const uint4*)(A + (size_t)gr*K + g*8);
            dst = smem + r*LDS_A + g*8;
        } else {
            int i2 = i - 512;
            int var = i2 >> 9, e = i2 & 511, r = e >> 2, g = e & 3;
            int gn = col0 + r;
            const __half* s = var ? Bl : Bh;
            if (gn < N) v = *(const uint4*)(s + (size_t)gn*K + g*8);
            dst = smem + (1 + var)*ABUF + r*LDS_A + g*8;
        }
        *(uint4*)dst = v;
    }
    __syncthreads();

    for (int kc = 0; kc < KC; kc++) {
        int b = kc & 1;
        // prefetch next chunk into regs
        uint4 pr[6];
        if (kc + 1 < KC) {
            #pragma unroll
            for (int j = 0; j < 6; j++) {
                int i = tid + j*256;
                pr[j] = make_uint4(0,0,0,0);
                if (i < 512) {
                    int r = i >> 2, g = i & 3;
                    int gr = row0 + r;
                    if (gr < M) pr[j] = *(const uint4*)(A + (size_t)gr*K + (kc+1)*32 + g*8);
                } else {
                    int i2 = i - 512;
                    int var = i2 >> 9, e = i2 & 511, r = e >> 2, g = e & 3;
                    int gn = col0 + r;
                    const __half* s = var ? Bl : Bh;
                    if (gn < N) pr[j] = *(const uint4*)(s + (size_t)gn*K + (kc+1)*32 + g*8);
                }
            }
        }

        const __half* bufp = smem + b*3*ABUF;
        #pragma unroll
        for (int ks = 0; ks < 2; ks++) {
            wmma::fragment<wmma::matrix_b, 16, 16, 16, __half, wmma::col_major> fbh[2], fbl[2];
            #pragma unroll
            for (int n = 0; n < 2; n++) {
                wmma::load_matrix_sync(fbh[n], bufp + 1*ABUF + (wn*32 + n*16)*LDS_A + ks*16, LDS_A);
                wmma::load_matrix_sync(fbl[n], bufp + 2*ABUF + (wn*32 + n*16)*LDS_A + ks*16, LDS_A);
            }
            #pragma unroll
            for (int m = 0; m < 4; m++) {
                wmma::fragment<wmma::matrix_a, 16, 16, 16, __half, wmma::row_major> fa;
                wmma::load_matrix_sync(fa, bufp + (wm*64 + m*16)*LDS_A + ks*16, LDS_A);
                #pragma unroll
                for (int n = 0; n < 2; n++) {
                    wmma::mma_sync(acc[m][n], fa, fbh[n], acc[m][n]);
                    wmma::mma_sync(acc[m][n], fa, fbl[n], acc[m][n]);
                }
            }
        }

        if (kc + 1 < KC) {
            __half* nbuf = smem + ((kc+1)&1)*3*ABUF;
            #pragma unroll
            for (int j = 0; j < 6; j++) {
                int i = tid + j*256;
                __half* dst;
                if (i < 512) {
                    int r = i >> 2, g = i & 3;
                    dst = nbuf + r*LDS_A + g*8;
                } else {
                    int i2 = i - 512;
                    int var = i2 >> 9, e = i2 & 511, r = e >> 2, g = e & 3;
                    dst = nbuf + (1 + var)*ABUF + r*LDS_A + g*8;
                }
                *(uint4*)dst = pr[j];
            }
        }
        __syncthreads();
    }

    // epilogue: store accs to smem (float, stride 36), then fused writes
    float* fsm = (float*)smem;
    float* wsm = fsm + wid * (64*36);
    #pragma unroll
    for (int m = 0; m < 4; m++)
        #pragma unroll
        for (int n = 0; n < 2; n++)
            wmma::store_matrix_sync(wsm + m*16*36 + n*16, acc[m][n], 36, wmma::mem_row_major);
    __syncwarp();
    int cc = lane;
    int gc = col0 + wn*32 + cc;
    if (gc < N) {
        float bv = HASBIAS ? bias[gc] : 0.f;
        for (int rr = 0; rr < 64; rr++) {
            int gr = row0 + wm*64 + rr;
            if (gr >= M) break;
            float v = wsm[rr*36 + cc];
            if (HASBIAS) v += bv;
            if (ACT)     v = gelu_tanh(v);
            if (HASRES)  v += res[(size_t)gr*ldc + gc];
            C[(size_t)gr*ldc + gc] = v;
        }
    }
}

__global__ void embed_init_kernel(const int* __restrict__ ids, const float* __restrict__ wte) {
    int idx = blockIdx.x * 256 + threadIdx.x;
    if (idx >= BB*SS*DD) return;
    int r = idx / DD, d = idx - r*DD;
    g_embeds[idx] = wte[(size_t)ids[r]*DD + d];
}
__global__ void build_x_kernel(const int* __restrict__ pos_ids, const float* __restrict__ wpe,
                               int qs, int qc) {
    int idx = blockIdx.x * 256 + threadIdx.x;
    if (idx >= BB*qc*DD) return;
    int r = idx / DD, d = idx - r*DD;
    int b = r / qc, t = r - b*qc;
    int s = qs + t;
    g_X[idx] = g_embeds[((size_t)b*SS + s)*DD + d] + wpe[(size_t)pos_ids[b*SS + s]*DD + d];
}
__global__ void ln_kernel(const float* __restrict__ in, float* __restrict__ out,
                          const float* __restrict__ gam, const float* __restrict__ bet,
                          int qc, int qs, int scatter) {
    int r = blockIdx.x;
    const float* x = in + (size_t)r*DD;
    int tid = threadIdx.x;
    float x0 = x[tid], x1 = x[tid+256], x2 = x[tid+512];
    __shared__ float sh[8];
    float s = wrsum(x0 + x1 + x2);
    if ((tid & 31) == 0) sh[tid >> 5] = s;
    __syncthreads();
    if (tid == 0) { float t = 0.f; for (int i = 0; i < 8; i++) t += sh[i]; sh[0] = t * (1.f/DD); }
    __syncthreads();
    float mean = sh[0];
    float d0 = x0 - mean, d1 = x1 - mean, d2 = x2 - mean;
    __syncthreads();
    float q = wrsum(d0*d0 + d1*d1 + d2*d2);
    if ((tid & 31) == 0) sh[tid >> 5] = q;
    __syncthreads();
    if (tid == 0) { float t = 0.f; for (int i = 0; i < 8; i++) t += sh[i]; sh[0] = rsqrtf(t*(1.f/DD) + 1e-5f); }
    __syncthreads();
    float rstd = sh[0];
    int orow = r;
    if (scatter) { int b = r / qc, t = r - b*qc; orow = b*SS + qs + t; }
    float* o = out + (size_t)orow*DD;
    o[tid]     = d0*rstd*gam[tid]     + bet[tid];
    o[tid+256] = d1*rstd*gam[tid+256] + bet[tid+256];
    o[tid+512] = d2*rstd*gam[tid+512] + bet[tid+512];
}

__global__ void gemv4_part(const float* __restrict__ A, const float* __restrict__ W, int N, int K) {
    __shared__ float Ash[4][128];
    int tid = threadIdx.x;
    int k0 = blockIdx.y * 128;
    for (int i = tid; i < 512; i += 128) {
        int r = i >> 7, k = i & 127;
        Ash[r][k] = A[(size_t)r*K + k0 + k];
    }
    __syncthreads();
    int n = blockIdx.x * 128 + tid;
    const float* wp = W + (size_t)k0*N + n;
    float s0=0.f, s1=0.f, s2=0.f, s3=0.f;
    #pragma unroll 8
    for (int k = 0; k < 128; k++) {
        float w = wp[(size_t)k*N];
        s0 = fmaf(w, Ash[0][k], s0);
        s1 = fmaf(w, Ash[1][k], s1);
        s2 = fmaf(w, Ash[2][k], s2);
        s3 = fmaf(w, Ash[3][k], s3);
    }
    float* pp = g_part + (size_t)blockIdx.y*4*DFFN + n;
    pp[0] = s0; pp[DFFN] = s1; pp[2*DFFN] = s2; pp[3*DFFN] = s3;
}
template<int ACT, int HASRES>
__global__ void gemv4_red(const float* __restrict__ bias, const float* __restrict__ res,
                          float* __restrict__ C, int N, int kch) {
    int n = blockIdx.x * 256 + threadIdx.x;
    if (n >= N) return;
    #pragma unroll
    for (int r = 0; r < 4; r++) {
        float s = bias[n];
        for (int c = 0; c < kch; c++) s += g_part[(size_t)c*4*DFFN + r*DFFN + n];
        if (ACT)    s = gelu_tanh(s);
        if (HASRES) s += res[(size_t)r*N + n];
        C[(size_t)r*N + n] = s;
    }
}

__global__ void kv_scatter(int l, int qs, int qc) {
    int idx = blockIdx.x * 256 + threadIdx.x;
    if (idx >= BB*qc*DD) return;
    int r = idx / DD, d = idx - r*DD;
    int b = r / qc, t = r - b*qc;
    int h = d >> 6, dh = d & 63;
    size_t c = ((size_t)((l*BB + b)*HH + h)*SS + qs + t)*DHH + dh;
    g_K[c] = g_QKV[(size_t)r*(3*DD) + DD   + d];
    g_V[c] = g_QKV[(size_t)r*(3*DD) + 2*DD + d];
}

__global__ void attn_kernel(int l, int qs, int qc, const int* __restrict__ amask) {
    __shared__ float qsh[8][4][64];
    int w = threadIdx.x >> 5, lane = threadIdx.x & 31;
    int nqt = (qc + 3) >> 2;
    int gw = blockIdx.x * 8 + w;
    if (gw >= nqt * BB * HH) return;
    int h = gw % HH, r1 = gw / HH, b = r1 % BB, qt = r1 / BB;
    int t0 = qt * 4;
    #pragma unroll
    for (int i = 0; i < 4; i++) {
        int t = t0 + i; if (t >= qc) t = qc - 1;
        const float* qp = g_QKV + (size_t)(b*qc + t)*(3*DD) + h*DHH;
        qsh[w][i][lane]      = qp[lane]      * ATT_SCALE;
        qsh[w][i][lane + 32] = qp[lane + 32] * ATT_SCALE;
    }
    __syncwarp();
    int qlast = min(t0 + 3, qc - 1);
    int qmax = qs + qlast;
    const float* kc = g_K + (size_t)((l*BB + b)*HH + h)*SS*DHH;
    const float* vc = g_V + (size_t)((l*BB + b)*HH + h)*SS*DHH;
    float m0=-1e30f,m1=-1e30f,m2=-1e30f,m3=-1e30f, dn0=0.f,dn1=0.f,dn2=0.f,dn3=0.f;
    float2 a0={0.f,0.f},a1={0.f,0.f},a2={0.f,0.f},a3={0.f,0.f};
    for (int j0 = 0; j0 <= qmax; j0 += 32) {
        int j = j0 + lane;
        float s0=-1e30f,s1=-1e30f,s2=-1e30f,s3=-1e30f;
        if (j <= qmax && amask[b*SS + j] != 0) {
            const float4* kr = (const float4*)(kc + (size_t)j*DHH);
            float u0=0.f,u1=0.f,u2=0.f,u3=0.f;
            #pragma unroll
            for (int i2 = 0; i2 < 16; i2++) {
                float4 kv = kr[i2];
                float4 q0 = *(const float4*)&qsh[w][0][i2*4];
                float4 q1 = *(const float4*)&qsh[w][1][i2*4];
                float4 q2 = *(const float4*)&qsh[w][2][i2*4];
                float4 q3 = *(const float4*)&qsh[w][3][i2*4];
                u0 += kv.x*q0.x + kv.y*q0.y + kv.z*q0.z + kv.w*q0.w;
                u1 += kv.x*q1.x + kv.y*q1.y + kv.z*q1.z + kv.w*q1.w;
                u2 += kv.x*q2.x + kv.y*q2.y + kv.z*q2.z + kv.w*q2.w;
                u3 += kv.x*q3.x + kv.y*q3.y + kv.z*q3.z + kv.w*q3.w;
            }
            s0 = (j <= qs + t0    ) ? u0 : -1e30f;
            s1 = (j <= qs + t0 + 1) ? u1 : -1e30f;
            s2 = (j <= qs + t0 + 2) ? u2 : -1e30f;
            s3 = (j <= qs + t0 + 3) ? u3 : -1e30f;
        }
        float n0 = fmaxf(m0, wrmax(s0)), n1 = fmaxf(m1, wrmax(s1));
        float n2 = fmaxf(m2, wrmax(s2)), n3 = fmaxf(m3, wrmax(s3));
        float p0 = __expf(s0-n0), p1 = __expf(s1-n1), p2 = __expf(s2-n2), p3 = __expf(s3-n3);
        float q0 = wrsum(p0), q1 = wrsum(p1), q2 = wrsum(p2), q3 = wrsum(p3);
        float e0 = __expf(m0-n0), e1 = __expf(m1-n1), e2 = __expf(m2-n2), e3 = __expf(m3-n3);
        dn0 = dn0*e0 + q0; a0.x *= e0; a0.y *= e0; m0 = n0;
        dn1 = dn1*e1 + q1; a1.x *= e1; a1.y *= e1; m1 = n1;
        dn2 = dn2*e2 + q2; a2.x *= e2; a2.y *= e2; m2 = n2;
        dn3 = dn3*e3 + q3; a3.x *= e3; a3.y *= e3; m3 = n3;
        int jc = min(32, qmax - j0 + 1);
        for (int jj = 0; jj < jc; jj++) {
            float2 vv = *(const float2*)(vc + (size_t)(j0 + jj)*DHH + lane*2);
            float w0 = __shfl_sync(0xffffffffu, p0, jj), w1 = __shfl_sync(0xffffffffu, p1, jj);
            float w2 = __shfl_sync(0xffffffffu, p2, jj), w3 = __shfl_sync(0xffffffffu, p3, jj);
            a0.x = fmaf(w0, vv.x, a0.x); a0.y = fmaf(w0, vv.y, a0.y);
            a1.x = fmaf(w1, vv.x, a1.x); a1.y = fmaf(w1, vv.y, a1.y);
            a2.x = fmaf(w2, vv.x, a2.x); a2.y = fmaf(w2, vv.y, a2.y);
            a3.x = fmaf(w3, vv.x, a3.x); a3.y = fmaf(w3, vv.y, a3.y);
        }
    }
    float2 ac[4] = {a0,a1,a2,a3};
    float dn[4] = {dn0,dn1,dn2,dn3};
    #pragma unroll
    for (int i = 0; i < 4; i++) {
        int t = t0 + i;
        if (t < qc) {
            float inv = 1.f / dn[i];
            *(float2*)&g_CTX[(size_t)(b*qc + t)*DD + h*DHH + lane*2] =
                make_float2(ac[i].x*inv, ac[i].y*inv);
        }
    }
}

__global__ void latent_update_kernel(int slot) {
    int idx = blockIdx.x * 256 + threadIdx.x;
    if (idx >= BB*DD) return;
    int b = idx / DD, d = idx - b*DD;
    g_embeds[((size_t)b*SS + slot)*DD + d] = g_HID[((size_t)b*SS + slot - 1)*DD + d];
}

// single-pass online-softmax NLL (poly exp on FMA pipe, one logits read)
__global__ void loss_row_kernel(const float* __restrict__ logits, const int* __restrict__ labels) {
    int r = blockIdx.x;
    int b = r / (SS-1), t = r - b*(SS-1);
    const float* x = logits + ((size_t)(b*SS + t))*VV;
    int tid = threadIdx.x;
    float mx = -1e30f, s = 0.f;
    for (int i = tid; i < VV; i += 256) {
        float v = x[i];
        float nm = fmaxf(mx, v);
        s = s * fexp(mx - nm) + fexp(v - nm);
        mx = nm;
    }
    #pragma unroll
    for (int o = 16; o; o >>= 1) {
        float om = __shfl_xor_sync(0xffffffffu, mx, o);
        float os = __shfl_xor_sync(0xffffffffu, s, o);
        float nm = fmaxf(mx, om);
        s = s * fexp(mx - nm) + os * fexp(om - nm);
        mx = nm;
    }
    __shared__ float shm[8], shs[8];
    if ((tid & 31) == 0) { shm[tid >> 5] = mx; shs[tid >> 5] = s; }
    __syncthreads();
    if (tid == 0) {
        float M2 = shm[0], S2 = shs[0];
        for (int i = 1; i < 8; i++) {
            float nm = fmaxf(M2, shm[i]);
            S2 = S2 * fexp(M2 - nm) + shs[i] * fexp(shm[i] - nm);
            M2 = nm;
        }
        g_nll[r] = logf(S2) + M2 - x[labels[b*SS + t + 1]];
    }
}
__global__ void loss_final_kernel(float* out) {
    int tid = threadIdx.x;
    __shared__ float sh[8];
    float s = 0.f;
    for (int i = tid; i < BB*(SS-1); i += 256) s += g_nll[i];
    s = wrsum(s);
    if ((tid & 31) == 0) sh[tid >> 5] = s;
    __syncthreads();
    if (tid == 0) {
        float t = 0.f; for (int i = 0; i < 8; i++) t += sh[i];
        out[0] = t / (float)(BB*(SS-1));
    }
}

extern "C" void kernel_launch(void* const* d_in, const int* in_sizes, int n_in,
                              void* d_out, int out_size) {
    const int*   input_ids = (const int*)d_in[0];
    const int*   amask     = (const int*)d_in[1];
    const int*   labels    = (const int*)d_in[2];
    const int*   pos_ids   = (const int*)d_in[3];
    const float* wte   = (const float*)d_in[4];
    const float* wpe   = (const float*)d_in[5];
    const float* ln1_g = (const float*)d_in[6];
    const float* ln1_b = (const float*)d_in[7];
    const float* Wqkv  = (const float*)d_in[8];
    const float* bqkv  = (const float*)d_in[9];
    const float* Wo    = (const float*)d_in[10];
    const float* bo    = (const float*)d_in[11];
    const float* ln2_g = (const float*)d_in[12];
    const float* ln2_b = (const float*)d_in[13];
    const float* W1    = (const float*)d_in[14];
    const float* b1    = (const float*)d_in[15];
    const float* W2    = (const float*)d_in[16];
    const float* b2    = (const float*)d_in[17];
    const float* lnf_g = (const float*)d_in[18];
    const float* lnf_b = (const float*)d_in[19];

    float* out    = (float*)d_out;
    float* logits = out + 1;

    cudaFuncSetAttribute(tgemm<0,0,0>, cudaFuncAttributeMaxDynamicSharedMemorySize, TG_SMEM);
    cudaFuncSetAttribute(tgemm<0,0,1>, cudaFuncAttributeMaxDynamicSharedMemorySize, TG_SMEM);
    cudaFuncSetAttribute(tgemm<0,1,1>, cudaFuncAttributeMaxDynamicSharedMemorySize, TG_SMEM);
    cudaFuncSetAttribute(tgemm<1,0,1>, cudaFuncAttributeMaxDynamicSharedMemorySize, TG_SMEM);

    float *pX, *pH, *pHID, *pQKV, *pCTX, *pG;
    cudaGetSymbolAddress((void**)&pX,   g_X);
    cudaGetSymbolAddress((void**)&pH,   g_H);
    cudaGetSymbolAddress((void**)&pHID, g_HID);
    cudaGetSymbolAddress((void**)&pQKV, g_QKV);
    cudaGetSymbolAddress((void**)&pCTX, g_CTX);
    cudaGetSymbolAddress((void**)&pG,   g_G);
    __half *pA, *pWh, *pWl, *pVh, *pVl;
    cudaGetSymbolAddress((void**)&pA,  g_Act);
    cudaGetSymbolAddress((void**)&pWh, g_Whi);
    cudaGetSymbolAddress((void**)&pWl, g_Wlo);
    cudaGetSymbolAddress((void**)&pVh, g_Vhi);
    cudaGetSymbolAddress((void**)&pVl, g_Vlo);

    embed_init_kernel<<<(BB*SS*DD + 255)/256, 256>>>(input_ids, wte);
    cvt_split_h<<<(VV*DD + 255)/256, 256>>>(wte, pVh, pVl, VV*DD);
    for (int l = 0; l < NLAYER; l++) {
        __half* wh = pWh + (size_t)l*PER_L;
        __half* wl = pWl + (size_t)l*PER_L;
        cvt_tr_h<<<dim3(2304/32, 768/32),  dim3(32,8)>>>(Wqkv + (size_t)l*DD*3*DD, wh + WQKV_T_OFF, wl + WQKV_T_OFF, 768, 2304);
        cvt_tr_h<<<dim3(768/32,  768/32),  dim3(32,8)>>>(Wo   + (size_t)l*DD*DD,   wh + WO_T_OFF,   wl + WO_T_OFF,   768, 768);
        cvt_tr_h<<<dim3(3072/32, 768/32),  dim3(32,8)>>>(W1   + (size_t)l*DD*DFFN, wh + W1_T_OFF,   wl + W1_T_OFF,   768, 3072);
        cvt_tr_h<<<dim3(768/32,  3072/32), dim3(32,8)>>>(W2   + (size_t)l*DFFN*DD, wh + W2_T_OFF,   wl + W2_T_OFF,   3072, 768);
    }

    const int QS[7] = {0, 64, 65, 66, 67, 68, 69};
    const int QC[7] = {64, 1,  1,  1,  1,  1,  SS - 69};

    for (int p = 0; p < 7; p++) {
        int qs = QS[p], qc = QC[p];
        int M = BB * qc;
        int mt = (M + 127)/128;

        build_x_kernel<<<(M*DD + 255)/256, 256>>>(pos_ids, wpe, qs, qc);

        for (int l = 0; l < NLAYER; l++) {
            __half* wh = pWh + (size_t)l*PER_L;
            __half* wl = pWl + (size_t)l*PER_L;
            const float* Wq  = Wqkv + (size_t)l*DD*3*DD;  const float* bq  = bqkv + (size_t)l*3*DD;
            const float* Wol = Wo   + (size_t)l*DD*DD;    const float* bol = bo   + (size_t)l*DD;
            const float* W1l = W1   + (size_t)l*DD*DFFN;  const float* b1l = b1   + (size_t)l*DFFN;
            const float* W2l = W2   + (size_t)l*DFFN*DD;  const float* b2l = b2   + (size_t)l*DD;

            ln_kernel<<<M, 256>>>(pX, pH, ln1_g + l*DD, ln1_b + l*DD, qc, qs, 0);

            if (qc == 1) {
                gemv4_part<<<dim3(3*DD/128, DD/128), 128>>>(pH, Wq, 3*DD, DD);
                gemv4_red<0,0><<<(3*DD + 255)/256, 256>>>(bq, 0, pQKV, 3*DD, DD/128);
            } else {
                cvt_half<<<(M*DD + 255)/256, 256>>>(pH, pA, M*DD);
                tgemm<0,0,1><<<dim3(mt, 18), 256, TG_SMEM>>>(pA, wh + WQKV_T_OFF, wl + WQKV_T_OFF,
                                                             bq, 0, pQKV, M, 3*DD, DD, 3*DD);
            }

            kv_scatter<<<(M*DD + 255)/256, 256>>>(l, qs, qc);
            attn_kernel<<<(((qc+3)/4)*BB*HH + 7)/8, 256>>>(l, qs, qc, amask);

            if (qc == 1) {
                gemv4_part<<<dim3(DD/128, DD/128), 128>>>(pCTX, Wol, DD, DD);
                gemv4_red<0,1><<<(DD + 255)/256, 256>>>(bol, pX, pX, DD, DD/128);
            } else {
                cvt_half<<<(M*DD + 255)/256, 256>>>(pCTX, pA, M*DD);
                tgemm<0,1,1><<<dim3(mt, 6), 256, TG_SMEM>>>(pA, wh + WO_T_OFF, wl + WO_T_OFF,
                                                            bol, pX, pX, M, DD, DD, DD);
            }

            ln_kernel<<<M, 256>>>(pX, pH, ln2_g + l*DD, ln2_b + l*DD, qc, qs, 0);

            if (qc == 1) {
                gemv4_part<<<dim3(DFFN/128, DD/128), 128>>>(pH, W1l, DFFN, DD);
                gemv4_red<1,0><<<(DFFN + 255)/256, 256>>>(b1l, 0, pG, DFFN, DD/128);
                gemv4_part<<<dim3(DD/128, DFFN/128), 128>>>(pG, W2l, DD, DFFN);
                gemv4_red<0,1><<<(DD + 255)/256, 256>>>(b2l, pX, pX, DD, DFFN/128);
            } else {
                cvt_half<<<(M*DD + 255)/256, 256>>>(pH, pA, M*DD);
                tgemm<1,0,1><<<dim3(mt, 24), 256, TG_SMEM>>>(pA, wh + W1_T_OFF, wl + W1_T_OFF,
                                                             b1l, 0, pG, M, DFFN, DD, DFFN);
                cvt_half<<<(M*DFFN + 255)/256, 256>>>(pG, pA, M*DFFN);
                tgemm<0,1,1><<<dim3(mt, 6), 256, TG_SMEM>>>(pA, wh + W2_T_OFF, wl + W2_T_OFF,
                                                            b2l, pX, pX, M, DD, DFFN, DD);
            }
        }

        ln_kernel<<<M, 256>>>(pX, pHID, lnf_g, lnf_b, qc, qs, 1);

        if (p < NLAT) latent_update_kernel<<<(BB*DD + 255)/256, 256>>>(LAT_START + p);
    }

    cvt_half<<<(BB*SS*DD + 255)/256, 256>>>(pHID, pA, BB*SS*DD);
    tgemm<0,0,0><<<dim3(BB*SS/128, (VV + 127)/128), 256, TG_SMEM>>>(pA, pVh, pVl,
                                                                    0, 0, logits, BB*SS, VV, DD, VV);

    loss_row_kernel<<<BB*(SS-1), 256>>>(logits, labels);
    loss_final_kernel<<<1, 256>>>(out);
}